// round 2
// baseline (speedup 1.0000x reference)
#include <cuda_runtime.h>
#include <cstdint>

#define B_ 4
#define S_ 2048
#define D_ 1024
#define H_ 16
#define A_ 64
#define PADW 68   // floats per padded row: keeps float4 alignment, staggers banks

// Scratch: projected q/k/v heads, [3][B][H][S][A] fp32 (~100 MB, static => allocation-guard safe)
__device__ float g_ph[3][(size_t)B_ * H_ * S_ * A_];

// ---------------------------------------------------------------------------
// Projection kernel: out[b,h,s,a] = sum_d x[b,s,d] * W[h,d,a] + bias[h,a]
// Grid: (S/64, B*H, 3), block 256. 64x64 output tile, K-chunks of 16.
// ---------------------------------------------------------------------------
__global__ __launch_bounds__(256) void proj_kernel(
    const float* __restrict__ q, const float* __restrict__ k, const float* __restrict__ v,
    const float* __restrict__ Wq, const float* __restrict__ bq,
    const float* __restrict__ Wk, const float* __restrict__ bk,
    const float* __restrict__ Wv, const float* __restrict__ bv)
{
    const int tid = threadIdx.x;
    const int stile = blockIdx.x;
    const int bh = blockIdx.y;
    const int b = bh / H_, h = bh % H_;
    const int z = blockIdx.z;

    const float* x    = (z == 0) ? q  : (z == 1) ? k  : v;
    const float* W    = (z == 0) ? Wq : (z == 1) ? Wk : Wv;
    const float* bias = (z == 0) ? bq : (z == 1) ? bk : bv;
    float* out = g_ph[z];

    __shared__ float Xs[16][PADW];  // k-major: Xs[d][s]
    __shared__ float Ws[16][PADW];  // Ws[d][a]

    const int ty = tid >> 4;        // 0..15 -> q-row group
    const int tx = tid & 15;        // 0..15 -> a-col group
    const int s0 = stile * 64;

    // loader indices
    const int lrow = tid >> 2;          // 0..63 (s within tile)
    const int lc4  = (tid & 3) << 2;    // 0,4,8,12 (d within chunk)
    const int wdd  = tid >> 4;          // 0..15 (d within chunk)
    const int wa0  = (tid & 15) << 2;   // 0..60 (a)

    const float* xbase = x + ((size_t)b * S_ + s0) * D_;
    const float* wbase = W + (size_t)h * D_ * A_;

    float acc[4][4];
    #pragma unroll
    for (int i = 0; i < 4; i++)
        #pragma unroll
        for (int j = 0; j < 4; j++) acc[i][j] = 0.0f;

    for (int d0 = 0; d0 < D_; d0 += 16) {
        __syncthreads();
        // load X tile 64s x 16d, store transposed (d-major)
        float4 qv = *(const float4*)(xbase + (size_t)lrow * D_ + d0 + lc4);
        Xs[lc4 + 0][lrow] = qv.x;
        Xs[lc4 + 1][lrow] = qv.y;
        Xs[lc4 + 2][lrow] = qv.z;
        Xs[lc4 + 3][lrow] = qv.w;
        // load W tile 16d x 64a, direct
        *(float4*)&Ws[wdd][wa0] = *(const float4*)(wbase + (size_t)(d0 + wdd) * A_ + wa0);
        __syncthreads();

        #pragma unroll
        for (int kk = 0; kk < 16; kk++) {
            float4 qf = *(float4*)&Xs[kk][ty << 2];
            float4 wf = *(float4*)&Ws[kk][tx << 2];
            float qa[4] = {qf.x, qf.y, qf.z, qf.w};
            float wa[4] = {wf.x, wf.y, wf.z, wf.w};
            #pragma unroll
            for (int i = 0; i < 4; i++)
                #pragma unroll
                for (int j = 0; j < 4; j++)
                    acc[i][j] += qa[i] * wa[j];
        }
    }

    // bias + store [B,H,S,A]
    float4 bv4 = *(const float4*)(bias + h * A_ + (tx << 2));
    float bb[4] = {bv4.x, bv4.y, bv4.z, bv4.w};
    float* obase = out + (((size_t)b * H_ + h) * S_ + s0) * A_;
    #pragma unroll
    for (int i = 0; i < 4; i++) {
        float4 o;
        o.x = acc[i][0] + bb[0];
        o.y = acc[i][1] + bb[1];
        o.z = acc[i][2] + bb[2];
        o.w = acc[i][3] + bb[3];
        *(float4*)(obase + (size_t)((ty << 2) + i) * A_ + (tx << 2)) = o;
    }
}

// ---------------------------------------------------------------------------
// Flash-attention kernel: one CTA = (b, h, 64-row Q tile). No S*S materialization.
// Online softmax, O accumulated in registers (4x4 per thread).
// Grid: (S/64, B*H), block 256, dynamic smem = 4 * 64 * PADW floats.
// ---------------------------------------------------------------------------
extern __shared__ float smem_attn[];

__global__ __launch_bounds__(256) void attn_kernel(float* __restrict__ out)
{
    float* Qs = smem_attn;               // [64a][PADW] a-major: Qs[a][s]
    float* Ks = Qs + 64 * PADW;          // [64a][PADW] a-major: Ks[a][kcol]
    float* Vs = Ks + 64 * PADW;          // [64k][PADW] k-major: Vs[k][a]
    float* Ps = Vs + 64 * PADW;          // [64q][PADW] q-major: Ps[q][k]

    const int tid = threadIdx.x;
    const int ty = tid >> 4;             // q-row group
    const int tx = tid & 15;             // col group (k for S-GEMM, a for PV)
    const int qtile = blockIdx.x;
    const int bh = blockIdx.y;
    const int b = bh / H_, h = bh % H_;

    const float* qh = g_ph[0] + (((size_t)b * H_ + h) * S_) * A_;
    const float* kh = g_ph[1] + (((size_t)b * H_ + h) * S_) * A_;
    const float* vh = g_ph[2] + (((size_t)b * H_ + h) * S_) * A_;

    // Load Q tile, transposed to a-major
    #pragma unroll
    for (int r = 0; r < 4; r++) {
        int idx = tid + r * 256;
        int s = idx >> 4;
        int a0 = (idx & 15) << 2;
        float4 qv = *(const float4*)(qh + (size_t)(qtile * 64 + s) * A_ + a0);
        Qs[(a0 + 0) * PADW + s] = qv.x;
        Qs[(a0 + 1) * PADW + s] = qv.y;
        Qs[(a0 + 2) * PADW + s] = qv.z;
        Qs[(a0 + 3) * PADW + s] = qv.w;
    }

    float m[4], l[4], acc[4][4];
    #pragma unroll
    for (int i = 0; i < 4; i++) {
        m[i] = -1e30f;
        l[i] = 0.0f;
        #pragma unroll
        for (int j = 0; j < 4; j++) acc[i][j] = 0.0f;
    }

    for (int t = 0; t < S_ / 64; t++) {
        __syncthreads();   // protect Ks/Vs/Ps from previous iteration readers
        // Load K tile (transposed, a-major) and V tile (direct, k-major)
        #pragma unroll
        for (int r = 0; r < 4; r++) {
            int idx = tid + r * 256;
            int kk = idx >> 4;
            int a0 = (idx & 15) << 2;
            float4 kv = *(const float4*)(kh + (size_t)(t * 64 + kk) * A_ + a0);
            Ks[(a0 + 0) * PADW + kk] = kv.x;
            Ks[(a0 + 1) * PADW + kk] = kv.y;
            Ks[(a0 + 2) * PADW + kk] = kv.z;
            Ks[(a0 + 3) * PADW + kk] = kv.w;
            float4 vv = *(const float4*)(vh + (size_t)(t * 64 + kk) * A_ + a0);
            *(float4*)&Vs[(size_t)kk * PADW + a0] = vv;
        }
        __syncthreads();

        // S = Q * K^T for this thread's 4x4 block
        float s4[4][4];
        #pragma unroll
        for (int i = 0; i < 4; i++)
            #pragma unroll
            for (int j = 0; j < 4; j++) s4[i][j] = 0.0f;

        #pragma unroll 8
        for (int a = 0; a < 64; a++) {
            float4 qf = *(float4*)&Qs[(size_t)a * PADW + (ty << 2)];
            float4 kf = *(float4*)&Ks[(size_t)a * PADW + (tx << 2)];
            float qa[4] = {qf.x, qf.y, qf.z, qf.w};
            float ka[4] = {kf.x, kf.y, kf.z, kf.w};
            #pragma unroll
            for (int i = 0; i < 4; i++)
                #pragma unroll
                for (int j = 0; j < 4; j++)
                    s4[i][j] += qa[i] * ka[j];
        }

        // Online softmax (per q-row; row spread over 16 tx lanes -> shfl width 16)
        #pragma unroll
        for (int i = 0; i < 4; i++) {
            float mt = fmaxf(fmaxf(s4[i][0], s4[i][1]), fmaxf(s4[i][2], s4[i][3]));
            #pragma unroll
            for (int off = 8; off; off >>= 1)
                mt = fmaxf(mt, __shfl_xor_sync(0xffffffffu, mt, off, 16));
            float mn = fmaxf(m[i], mt);
            float corr = __expf(m[i] - mn);
            m[i] = mn;
            float rs = 0.0f;
            #pragma unroll
            for (int j = 0; j < 4; j++) {
                s4[i][j] = __expf(s4[i][j] - mn);
                rs += s4[i][j];
            }
            #pragma unroll
            for (int off = 8; off; off >>= 1)
                rs += __shfl_xor_sync(0xffffffffu, rs, off, 16);
            l[i] = l[i] * corr + rs;
            #pragma unroll
            for (int j = 0; j < 4; j++) acc[i][j] *= corr;
            *(float4*)&Ps[(size_t)((ty << 2) + i) * PADW + (tx << 2)] =
                make_float4(s4[i][0], s4[i][1], s4[i][2], s4[i][3]);
        }
        __syncthreads();

        // O += P @ V  (thread owns q-rows ty*4.., a-cols tx*4..)
        #pragma unroll 4
        for (int k4 = 0; k4 < 16; k4++) {
            float pfi[4][4];
            #pragma unroll
            for (int i = 0; i < 4; i++) {
                float4 pf = *(float4*)&Ps[(size_t)((ty << 2) + i) * PADW + (k4 << 2)];
                pfi[i][0] = pf.x; pfi[i][1] = pf.y; pfi[i][2] = pf.z; pfi[i][3] = pf.w;
            }
            #pragma unroll
            for (int kk = 0; kk < 4; kk++) {
                float4 vf = *(float4*)&Vs[(size_t)((k4 << 2) + kk) * PADW + (tx << 2)];
                float va0 = vf.x, va1 = vf.y, va2 = vf.z, va3 = vf.w;
                #pragma unroll
                for (int i = 0; i < 4; i++) {
                    acc[i][0] += pfi[i][kk] * va0;
                    acc[i][1] += pfi[i][kk] * va1;
                    acc[i][2] += pfi[i][kk] * va2;
                    acc[i][3] += pfi[i][kk] * va3;
                }
            }
        }
    }

    // Normalize and store: out[b, s, h*A + a]
    #pragma unroll
    for (int i = 0; i < 4; i++) {
        float inv = 1.0f / l[i];
        int s = qtile * 64 + (ty << 2) + i;
        float4 o;
        o.x = acc[i][0] * inv;
        o.y = acc[i][1] * inv;
        o.z = acc[i][2] * inv;
        o.w = acc[i][3] * inv;
        *(float4*)(out + ((size_t)b * S_ + s) * (H_ * A_) + h * A_ + (tx << 2)) = o;
    }
}

// ---------------------------------------------------------------------------
extern "C" void kernel_launch(void* const* d_in, const int* in_sizes, int n_in,
                              void* d_out, int out_size)
{
    const float* q  = (const float*)d_in[0];
    const float* k  = (const float*)d_in[1];
    const float* v  = (const float*)d_in[2];
    const float* Wq = (const float*)d_in[3];
    const float* bq = (const float*)d_in[4];
    const float* Wk = (const float*)d_in[5];
    const float* bk = (const float*)d_in[6];
    const float* Wv = (const float*)d_in[7];
    const float* bv = (const float*)d_in[8];

    const int attn_smem = 4 * 64 * PADW * (int)sizeof(float);  // 69632 B
    cudaFuncSetAttribute(attn_kernel, cudaFuncAttributeMaxDynamicSharedMemorySize, attn_smem);

    dim3 pgrid(S_ / 64, B_ * H_, 3);
    proj_kernel<<<pgrid, 256>>>(q, k, v, Wq, bq, Wk, bk, Wv, bv);

    dim3 agrid(S_ / 64, B_ * H_);
    attn_kernel<<<agrid, 256, attn_smem>>>((float*)d_out);
}

// round 6
// speedup vs baseline: 1.3469x; 1.3469x over previous
#include <cuda_runtime.h>
#include <cstdint>

#define B_ 4
#define S_ 2048
#define D_ 1024
#define H_ 16
#define A_ 64

typedef unsigned long long u64t;

// Scratch: projected q/k/v heads, [3][B][H][S][A] fp32 (static => allocation-guard safe)
__device__ float g_ph[3][(size_t)B_ * H_ * S_ * A_];

// ---------------------------------------------------------------------------
// Packed fp32x2 helpers (plain sm_100 PTX ISA 8.6 — NOT an 'a' feature)
// ---------------------------------------------------------------------------
__device__ __forceinline__ u64t pk2(float lo, float hi) {
    u64t d;
    asm("mov.b64 %0, {%1, %2};" : "=l"(d) : "f"(lo), "f"(hi));
    return d;
}
__device__ __forceinline__ void upk2(float& lo, float& hi, u64t d) {
    asm("mov.b64 {%0, %1}, %2;" : "=f"(lo), "=f"(hi) : "l"(d));
}
__device__ __forceinline__ void fma2(u64t& d, u64t a, u64t b) {
    asm("fma.rn.f32x2 %0, %1, %2, %3;" : "=l"(d) : "l"(a), "l"(b), "l"(d));
}
__device__ __forceinline__ u64t mul2(u64t a, u64t b) {
    u64t d;
    asm("mul.rn.f32x2 %0, %1, %2;" : "=l"(d) : "l"(a), "l"(b));
    return d;
}

// ---------------------------------------------------------------------------
// Projection: out[b,h,s,a] = sum_d x[b,s,d] * W[h,d,a] + bias[h,a]
// CTA tile: 128 rows x 128 cols (2 heads), 256 threads, 8x8/thread (f32x2 pairs).
// Grid (B*S/128 = 64, H/2 = 8, 3), block 256.
// ---------------------------------------------------------------------------
#define PKX 132   // padded row length for proj smem

__global__ __launch_bounds__(256, 2) void proj_kernel(
    const float* __restrict__ q, const float* __restrict__ k, const float* __restrict__ v,
    const float* __restrict__ Wq, const float* __restrict__ bq,
    const float* __restrict__ Wk, const float* __restrict__ bk,
    const float* __restrict__ Wv, const float* __restrict__ bv)
{
    const int tid = threadIdx.x;
    const int ty = tid >> 4;          // 0..15 -> 8-row group
    const int tx = tid & 15;          // 0..15 -> two 4-col groups (tx*4, 64+tx*4)
    const int m0 = blockIdx.x * 128;  // flattened (b*S + s) row base
    const int h0 = blockIdx.y * 2;
    const int z = blockIdx.z;

    const float* x    = (z == 0) ? q  : (z == 1) ? k  : v;
    const float* W    = (z == 0) ? Wq : (z == 1) ? Wk : Wv;
    const float* bias = (z == 0) ? bq : (z == 1) ? bk : bv;

    __shared__ float Xs[16][PKX];     // d-major: Xs[d][row]
    __shared__ float Ws[16][PKX];     // Ws[d][n], n in [0,128): h = h0 + n/64, a = n%64

    const float* xbase = x + (size_t)m0 * D_;
    const float* wb = W + (size_t)h0 * D_ * A_;

    u64t acc2[8][4];
    #pragma unroll
    for (int i = 0; i < 8; i++)
        #pragma unroll
        for (int p = 0; p < 4; p++) acc2[i][p] = 0ull;

    for (int d0 = 0; d0 < D_; d0 += 16) {
        __syncthreads();
        // X tile: 128 rows x 16 d, transposed store
        #pragma unroll
        for (int j = 0; j < 2; j++) {
            int idx = tid + j * 256;            // [0,512)
            int row = idx >> 2, c = (idx & 3) << 2;
            float4 xv = *(const float4*)(xbase + (size_t)row * D_ + d0 + c);
            Xs[c + 0][row] = xv.x;
            Xs[c + 1][row] = xv.y;
            Xs[c + 2][row] = xv.z;
            Xs[c + 3][row] = xv.w;
        }
        // W tile: 16 d x 128 n (two heads side by side)
        #pragma unroll
        for (int j = 0; j < 2; j++) {
            int idx = tid + j * 256;            // [0,512)
            int d = idx >> 5, n4 = (idx & 31) << 2;
            int hh = n4 >> 6, a = n4 & 63;
            *(float4*)&Ws[d][n4] =
                *(const float4*)(wb + (size_t)hh * D_ * A_ + (size_t)(d0 + d) * A_ + a);
        }
        __syncthreads();

        #pragma unroll
        for (int kk = 0; kk < 16; kk++) {
            float4 q0 = *(float4*)&Xs[kk][ty * 8];
            float4 q1 = *(float4*)&Xs[kk][ty * 8 + 4];
            float4 w0 = *(float4*)&Ws[kk][tx * 4];
            float4 w1 = *(float4*)&Ws[kk][64 + tx * 4];
            u64t w2[4] = {pk2(w0.x, w0.y), pk2(w0.z, w0.w),
                          pk2(w1.x, w1.y), pk2(w1.z, w1.w)};
            float qa[8] = {q0.x, q0.y, q0.z, q0.w, q1.x, q1.y, q1.z, q1.w};
            #pragma unroll
            for (int i = 0; i < 8; i++) {
                u64t qq = pk2(qa[i], qa[i]);
                #pragma unroll
                for (int p = 0; p < 4; p++) fma2(acc2[i][p], qq, w2[p]);
            }
        }
    }

    // epilogue: bias + store [B,H,S,A]
    float4 b0 = *(const float4*)(bias + h0 * A_ + tx * 4);
    float4 b1 = *(const float4*)(bias + (h0 + 1) * A_ + tx * 4);
    #pragma unroll
    for (int i = 0; i < 8; i++) {
        int row = m0 + ty * 8 + i;
        int b = row >> 11, s = row & (S_ - 1);
        float o0, o1, o2, o3;
        upk2(o0, o1, acc2[i][0]);
        upk2(o2, o3, acc2[i][1]);
        float4 r0 = make_float4(o0 + b0.x, o1 + b0.y, o2 + b0.z, o3 + b0.w);
        *(float4*)(g_ph[z] + ((((size_t)b * H_ + h0) * S_ + s) << 6) + tx * 4) = r0;
        upk2(o0, o1, acc2[i][2]);
        upk2(o2, o3, acc2[i][3]);
        float4 r1 = make_float4(o0 + b1.x, o1 + b1.y, o2 + b1.z, o3 + b1.w);
        *(float4*)(g_ph[z] + ((((size_t)b * H_ + h0 + 1) * S_ + s) << 6) + tx * 4) = r1;
    }
}

// ---------------------------------------------------------------------------
// Flash attention: CTA = (b,h, 128-row Q tile), 128-col K tiles, 256 threads,
// 8x8/thread S-GEMM + 8x4/thread PV-GEMM, f32x2 packed FMA, online softmax.
// Grid (S/128 = 16, B*H = 64), block 256.
// ---------------------------------------------------------------------------
#define PQK 132   // Qs/Ks/Ps padded row (floats)
#define PV_ 68    // Vs padded row
#define QS_OFF 0
#define KS_OFF (64 * PQK)
#define VS_OFF (KS_OFF + 64 * PQK)
#define PS_OFF (VS_OFF + 128 * PV_)
#define ATTN_SMEM_FLOATS (PS_OFF + 128 * PQK)

extern __shared__ float smem_attn[];

__global__ __launch_bounds__(256, 1) void attn_kernel(float* __restrict__ out)
{
    float* Qs = smem_attn + QS_OFF;   // [64 a][PQK] : Qs[a][row]
    float* Ks = smem_attn + KS_OFF;   // [64 a][PQK] : Ks[a][col]
    float* Vs = smem_attn + VS_OFF;   // [128 k][PV_]: Vs[k][a]
    float* Ps = smem_attn + PS_OFF;   // [128 q][PQK]: Ps[q][col]

    const int tid = threadIdx.x;
    const int ty = tid >> 4;          // 0..15 -> 8 q-rows
    const int tx = tid & 15;          // 0..15 -> col groups
    const int qtile = blockIdx.x;
    const int bh = blockIdx.y;
    const int b = bh / H_, h = bh % H_;

    const float* qh = g_ph[0] + (((size_t)b * H_ + h) * S_) * A_;
    const float* kh = g_ph[1] + (((size_t)b * H_ + h) * S_) * A_;
    const float* vh = g_ph[2] + (((size_t)b * H_ + h) * S_) * A_;

    // Load Q tile (128 rows x 64 a), transposed to a-major
    #pragma unroll
    for (int j = 0; j < 8; j++) {
        int idx = tid + j * 256;            // [0,2048)
        int row = idx >> 4, a4 = (idx & 15) << 2;
        float4 qv = *(const float4*)(qh + (size_t)(qtile * 128 + row) * A_ + a4);
        Qs[(a4 + 0) * PQK + row] = qv.x;
        Qs[(a4 + 1) * PQK + row] = qv.y;
        Qs[(a4 + 2) * PQK + row] = qv.z;
        Qs[(a4 + 3) * PQK + row] = qv.w;
    }

    float m[8], l[8];
    u64t o2[8][2];
    #pragma unroll
    for (int i = 0; i < 8; i++) {
        m[i] = -1e30f;
        l[i] = 0.0f;
        o2[i][0] = 0ull;
        o2[i][1] = 0ull;
    }

    for (int t = 0; t < S_ / 128; t++) {
        __syncthreads();   // protect Ks/Vs/Ps from previous-iteration readers
        // K (transposed, a-major) + V (direct)
        #pragma unroll
        for (int j = 0; j < 8; j++) {
            int idx = tid + j * 256;        // [0,2048)
            int krow = idx >> 4, a4 = (idx & 15) << 2;
            float4 kv = *(const float4*)(kh + (size_t)(t * 128 + krow) * A_ + a4);
            Ks[(a4 + 0) * PQK + krow] = kv.x;
            Ks[(a4 + 1) * PQK + krow] = kv.y;
            Ks[(a4 + 2) * PQK + krow] = kv.z;
            Ks[(a4 + 3) * PQK + krow] = kv.w;
            float4 vv = *(const float4*)(vh + (size_t)(t * 128 + krow) * A_ + a4);
            *(float4*)&Vs[krow * PV_ + a4] = vv;
        }
        __syncthreads();

        // S = Q K^T : 8 rows x 8 cols per thread (cols tx*4..+3 and 64+tx*4..+3)
        u64t s2[8][4];
        #pragma unroll
        for (int i = 0; i < 8; i++)
            #pragma unroll
            for (int p = 0; p < 4; p++) s2[i][p] = 0ull;

        #pragma unroll 4
        for (int a = 0; a < 64; a++) {
            float4 q0 = *(float4*)&Qs[a * PQK + ty * 8];
            float4 q1 = *(float4*)&Qs[a * PQK + ty * 8 + 4];
            float4 k0 = *(float4*)&Ks[a * PQK + tx * 4];
            float4 k1 = *(float4*)&Ks[a * PQK + 64 + tx * 4];
            u64t k2[4] = {pk2(k0.x, k0.y), pk2(k0.z, k0.w),
                          pk2(k1.x, k1.y), pk2(k1.z, k1.w)};
            float qa[8] = {q0.x, q0.y, q0.z, q0.w, q1.x, q1.y, q1.z, q1.w};
            #pragma unroll
            for (int i = 0; i < 8; i++) {
                u64t qq = pk2(qa[i], qa[i]);
                #pragma unroll
                for (int p = 0; p < 4; p++) fma2(s2[i][p], qq, k2[p]);
            }
        }

        // Online softmax per q-row (row spread over 16 tx lanes; shfl width 16)
        #pragma unroll
        for (int i = 0; i < 8; i++) {
            float sv[8];
            upk2(sv[0], sv[1], s2[i][0]);
            upk2(sv[2], sv[3], s2[i][1]);
            upk2(sv[4], sv[5], s2[i][2]);
            upk2(sv[6], sv[7], s2[i][3]);
            float mt = sv[0];
            #pragma unroll
            for (int j = 1; j < 8; j++) mt = fmaxf(mt, sv[j]);
            #pragma unroll
            for (int off = 8; off; off >>= 1)
                mt = fmaxf(mt, __shfl_xor_sync(0xffffffffu, mt, off, 16));
            float mn = fmaxf(m[i], mt);
            float corr = __expf(m[i] - mn);
            m[i] = mn;
            float rs = 0.0f;
            #pragma unroll
            for (int j = 0; j < 8; j++) {
                sv[j] = __expf(sv[j] - mn);
                rs += sv[j];
            }
            #pragma unroll
            for (int off = 8; off; off >>= 1)
                rs += __shfl_xor_sync(0xffffffffu, rs, off, 16);
            l[i] = l[i] * corr + rs;
            u64t c2 = pk2(corr, corr);
            o2[i][0] = mul2(o2[i][0], c2);
            o2[i][1] = mul2(o2[i][1], c2);
            int prow = ty * 8 + i;
            *(float4*)&Ps[prow * PQK + tx * 4] = make_float4(sv[0], sv[1], sv[2], sv[3]);
            *(float4*)&Ps[prow * PQK + 64 + tx * 4] = make_float4(sv[4], sv[5], sv[6], sv[7]);
        }
        __syncthreads();

        // O += P V : 8 rows x 4 a-cols per thread (cols tx*4..+3)
        #pragma unroll 2
        for (int k4 = 0; k4 < 32; k4++) {
            float4 p4[8];
            #pragma unroll
            for (int i = 0; i < 8; i++)
                p4[i] = *(float4*)&Ps[(ty * 8 + i) * PQK + k4 * 4];
            #pragma unroll
            for (int kk = 0; kk < 4; kk++) {
                float4 vv = *(float4*)&Vs[(k4 * 4 + kk) * PV_ + tx * 4];
                u64t v2a = pk2(vv.x, vv.y);
                u64t v2b = pk2(vv.z, vv.w);
                #pragma unroll
                for (int i = 0; i < 8; i++) {
                    float pv = (kk == 0) ? p4[i].x : (kk == 1) ? p4[i].y
                             : (kk == 2) ? p4[i].z : p4[i].w;
                    u64t pp = pk2(pv, pv);
                    fma2(o2[i][0], pp, v2a);
                    fma2(o2[i][1], pp, v2b);
                }
            }
        }
    }

    // Normalize and store: out[b, s, h*A + a]
    #pragma unroll
    for (int i = 0; i < 8; i++) {
        float inv = 1.0f / l[i];
        int s = qtile * 128 + ty * 8 + i;
        float o0, o1, o2v, o3;
        upk2(o0, o1, o2[i][0]);
        upk2(o2v, o3, o2[i][1]);
        float4 r = make_float4(o0 * inv, o1 * inv, o2v * inv, o3 * inv);
        *(float4*)(out + ((size_t)b * S_ + s) * (H_ * A_) + h * A_ + tx * 4) = r;
    }
}

// ---------------------------------------------------------------------------
extern "C" void kernel_launch(void* const* d_in, const int* in_sizes, int n_in,
                              void* d_out, int out_size)
{
    const float* q  = (const float*)d_in[0];
    const float* k  = (const float*)d_in[1];
    const float* v  = (const float*)d_in[2];
    const float* Wq = (const float*)d_in[3];
    const float* bq = (const float*)d_in[4];
    const float* Wk = (const float*)d_in[5];
    const float* bk = (const float*)d_in[6];
    const float* Wv = (const float*)d_in[7];
    const float* bv = (const float*)d_in[8];

    const int attn_smem = ATTN_SMEM_FLOATS * (int)sizeof(float);   // 169,984 B
    cudaFuncSetAttribute(attn_kernel, cudaFuncAttributeMaxDynamicSharedMemorySize, attn_smem);

    dim3 pgrid(B_ * S_ / 128, H_ / 2, 3);
    proj_kernel<<<pgrid, 256>>>(q, k, v, Wq, bq, Wk, bk, Wv, bv);

    dim3 agrid(S_ / 128, B_ * H_);
    attn_kernel<<<agrid, 256, attn_smem>>>((float*)d_out);
}